// round 14
// baseline (speedup 1.0000x reference)
#include <cuda_runtime.h>
#include <cuda_fp16.h>
#include <cstdint>
#include <math.h>

#define B_SZ 8
#define S_SZ 2048
#define D_SZ 1024
#define H_SZ 2048
#define M_TOT 16384

// ---------------- scratch (device globals) ------------------------------------
__device__ __half g_Xh[(size_t)M_TOT * D_SZ];    // X as fp16
__device__ __half g_W1T[(size_t)H_SZ * D_SZ];    // [N=2048][K=1024] fp16
__device__ __half g_W2T[(size_t)D_SZ * H_SZ];    // [N=1024][K=2048] fp16
__device__ __half g_T[(size_t)M_TOT * H_SZ];     // GEMM1 out, fp16

// ---------------- small PTX helpers (sm_80-level, compute_103-safe) ------------
static __device__ __forceinline__ uint32_t smem_u32(const void* p) {
    uint32_t a;
    asm("{ .reg .u64 t; cvta.to.shared.u64 t, %1; cvt.u32.u64 %0, t; }"
        : "=r"(a) : "l"(p));
    return a;
}
static __device__ __forceinline__ void cpasync16(uint32_t dst, const void* src) {
    asm volatile("cp.async.cg.shared.global [%0], [%1], 16;"
                 :: "r"(dst), "l"(src) : "memory");
}
static __device__ __forceinline__ void cp_commit() {
    asm volatile("cp.async.commit_group;" ::: "memory");
}
template<int N>
static __device__ __forceinline__ void cp_wait() {
    asm volatile("cp.async.wait_group %0;" :: "n"(N) : "memory");
}
static __device__ __forceinline__ void ldsm4(uint32_t* r, uint32_t addr) {
    asm volatile("ldmatrix.sync.aligned.m8n8.x4.shared.b16 {%0,%1,%2,%3}, [%4];"
                 : "=r"(r[0]), "=r"(r[1]), "=r"(r[2]), "=r"(r[3]) : "r"(addr));
}
static __device__ __forceinline__ void mma16816(float* d, const uint32_t* a,
                                                uint32_t b0, uint32_t b1) {
    asm volatile(
        "mma.sync.aligned.m16n8k16.row.col.f32.f16.f16.f32 "
        "{%0,%1,%2,%3}, {%4,%5,%6,%7}, {%8,%9}, {%0,%1,%2,%3};"
        : "+f"(d[0]), "+f"(d[1]), "+f"(d[2]), "+f"(d[3])
        : "r"(a[0]), "r"(a[1]), "r"(a[2]), "r"(a[3]), "r"(b0), "r"(b1));
}

// ---------------- prep kernels ------------------------------------------------
__global__ void convert_half_kernel(const float* __restrict__ X,
                                    __half* __restrict__ H, int n4) {
    int stride = gridDim.x * blockDim.x;
    for (int i = blockIdx.x * blockDim.x + threadIdx.x; i < n4; i += stride) {
        float4 v = reinterpret_cast<const float4*>(X)[i];
        uint2 p;
        p.x = ((uint32_t)__half_as_ushort(__float2half_rn(v.y)) << 16)
            | __half_as_ushort(__float2half_rn(v.x));
        p.y = ((uint32_t)__half_as_ushort(__float2half_rn(v.w)) << 16)
            | __half_as_ushort(__float2half_rn(v.z));
        reinterpret_cast<uint2*>(H)[i] = p;
    }
}

// W [R][C] fp32 -> WT [C][R] fp16
__global__ void transpose_half_kernel(const float* __restrict__ W,
                                      __half* __restrict__ T,
                                      int R, int C) {
    __shared__ float t[32][33];
    int c0 = blockIdx.x * 32, r0 = blockIdx.y * 32;
    int tx = threadIdx.x, ty = threadIdx.y;
    #pragma unroll
    for (int i = ty; i < 32; i += 8)
        t[i][tx] = W[(size_t)(r0 + i) * C + c0 + tx];
    __syncthreads();
    #pragma unroll
    for (int i = ty; i < 32; i += 8) {
        float x = t[tx][i];                 // = W[r0+tx][c0+i]
        T[(size_t)(c0 + i) * R + r0 + tx] = __float2half_rn(x);
    }
}

__global__ void copy_first_token_kernel(const float* __restrict__ X,
                                        float* __restrict__ out) {
    int i = blockIdx.x * blockDim.x + threadIdx.x;
    if (i >= B_SZ * D_SZ) return;
    int b = i >> 10, d = i & 1023;
    size_t off = ((size_t)b * S_SZ) * D_SZ + d;
    out[off] = X[off];
}

// ---------------- HMMA (mma.sync) fp16 GEMM ------------------------------------
// C[M,N] = act(A·B^T + bias); A, B fp16 K-major; fp32 accum.
// CTA tile 128x128x64, 3-stage cp.async (96KB), 4 warps of 64x64, 2 CTAs/SM.
#define GBM 128
#define GBN 128
#define GBK 64
#define NTHR 128
#define STAGES 3
#define STG_B 32768                 // A 16K | B 16K
#define B_O   16384
#define SMEM_REQ (STAGES * STG_B)   // 96KB

template<int K_TOT, bool FUSE1>
__global__ __launch_bounds__(NTHR, 2)
void hmma_gemm(const __half* __restrict__ Amat,
               const __half* __restrict__ Bmat,
               const float* __restrict__ bias,
               __half* __restrict__ OutT,
               float* __restrict__ OutF,
               int Ncols)
{
    extern __shared__ char smem_raw[];
    const uint32_t sbase = smem_u32(smem_raw);

    const int tid = threadIdx.x;
    const int wid = tid >> 5;
    const int l   = tid & 31;
    const int m0  = blockIdx.y * GBM;
    const int n0  = blockIdx.x * GBN;
    const int wm  = wid & 1;        // 2 warp-rows of 64
    const int wn  = wid >> 1;       // 2 warp-cols of 64

    // ---- global->smem load plan: 16 x 16B units per thread ------------------
    // rows are 128B (64 fp16). thread: r0 = tid>>3 (0..15), cc = tid&7.
    // A units i=0..7: rows r0 + 16i ; B units i=8..15: rows r0 + 16(i-8)
    const char* pmA;
    const char* pmB;
    {
        const int r0 = tid >> 3, cc = tid & 7;
        pmA = (const char*)(Amat + (size_t)(m0 + r0) * K_TOT) + cc * 16;
        pmB = (const char*)(Bmat + (size_t)(n0 + r0) * K_TOT) + cc * 16;
    }
    // swizzle: chunk' = cc ^ (row & 7); (row+16j)&7 == r0&7, so s0 is constant
    const uint32_t s0 = (uint32_t)((tid >> 3) * 128)
                      + ((uint32_t)((tid & 7) ^ ((tid >> 3) & 7)) << 4);

    // ---- ldmatrix address pieces -------------------------------------------
    uint32_t aAddr[4], aSw[4], bAddr[4], bSw[4];
    #pragma unroll
    for (int mi = 0; mi < 4; ++mi) {
        int row = wm * 64 + mi * 16 + ((l >> 3) & 1) * 8 + (l & 7);
        aAddr[mi] = (uint32_t)row * 128;
        aSw[mi]   = (uint32_t)(row & 7);
    }
    #pragma unroll
    for (int ni = 0; ni < 4; ++ni) {
        int row = wn * 64 + ni * 16 + ((l >> 4) & 1) * 8 + (l & 7);
        bAddr[ni] = B_O + (uint32_t)row * 128;
        bSw[ni]   = (uint32_t)(row & 7);
    }
    const uint32_t a_c = (uint32_t)(l >> 4);
    const uint32_t b_c = (uint32_t)((l >> 3) & 1);

    float acc[4][8][4];
    #pragma unroll
    for (int i = 0; i < 4; ++i)
        #pragma unroll
        for (int j = 0; j < 8; ++j)
            #pragma unroll
            for (int q = 0; q < 4; ++q) acc[i][j][q] = 0.f;

    uint32_t Ah[4][4], Bh[4][4];

    constexpr int NC = K_TOT / GBK;

    // unit i: 0..7 -> A row-block i; 8..15 -> B row-block i-8
    auto unit_src = [&](int i, int chunk) -> const char* {
        const char* base = (i < 8) ? pmA : pmB;
        const int kb = i & 7;
        return base + (size_t)kb * 16 * K_TOT * 2 + (size_t)chunk * 128;
    };
    auto unit_dst = [&](int i, uint32_t sb) -> uint32_t {
        const int kb = i & 7;
        const uint32_t mb = (i < 8) ? 0u : B_O;
        return sb + mb + (uint32_t)kb * 2048 + s0;
    };

    // prologue: fill stages 0 and 1 (chunks 0, 1)
    #pragma unroll
    for (int s = 0; s < 2; ++s) {
        const uint32_t sb = sbase + (uint32_t)s * STG_B;
        #pragma unroll
        for (int i = 0; i < 16; ++i)
            cpasync16(unit_dst(i, sb), unit_src(i, s));
        cp_commit();
    }

    #pragma unroll 1
    for (int c = 0; c < NC; ++c) {
        cp_wait<1>();                // chunk c complete (issued 2 chunks ago)
        __syncthreads();

        // prefetch chunk c+2 into the slot vacated by chunk c-1
        const int pf = c + 2;
        if (pf < NC) {
            const uint32_t sbpf = sbase + (uint32_t)(pf % STAGES) * STG_B;
            #pragma unroll
            for (int i = 0; i < 16; ++i)
                cpasync16(unit_dst(i, sbpf), unit_src(i, pf));
        }
        cp_commit();

        const uint32_t sb = sbase + (uint32_t)(c % STAGES) * STG_B;
        #pragma unroll
        for (int step = 0; step < 4; ++step) {
            const uint32_t acx = (uint32_t)(step * 2) + a_c;
            const uint32_t bcx = (uint32_t)(step * 2) + b_c;
            #pragma unroll
            for (int mi = 0; mi < 4; ++mi)
                ldsm4(Ah[mi], sb + aAddr[mi] + ((acx ^ aSw[mi]) << 4));
            #pragma unroll
            for (int ni = 0; ni < 4; ++ni)
                ldsm4(Bh[ni], sb + bAddr[ni] + ((bcx ^ bSw[ni]) << 4));
            #pragma unroll
            for (int mi = 0; mi < 4; ++mi) {
                #pragma unroll
                for (int nj = 0; nj < 8; ++nj) {
                    const int ni = nj >> 1, h = (nj & 1) * 2;
                    mma16816(acc[mi][nj], Ah[mi], Bh[ni][h], Bh[ni][h + 1]);
                }
            }
        }
    }

    // ---- epilogue -----------------------------------------------------------
    const int r_base = m0 + wm * 64 + (l >> 2);
    const int c_base = n0 + wn * 64 + (l & 3) * 2;
    #pragma unroll
    for (int mi = 0; mi < 4; ++mi) {
        #pragma unroll
        for (int nj = 0; nj < 8; ++nj) {
            const int col = c_base + nj * 8;
            const float bb0 = __ldg(bias + col);
            const float bb1 = __ldg(bias + col + 1);
            #pragma unroll
            for (int hh = 0; hh < 2; ++hh) {
                const int row = r_base + mi * 16 + hh * 8;
                float t0 = acc[mi][nj][hh * 2 + 0] + bb0;
                float t1 = acc[mi][nj][hh * 2 + 1] + bb1;
                if (FUSE1) {
                    t0 = 0.5f * t0 * (1.0f + erff(t0 * 0.70710678118654752f));
                    t1 = 0.5f * t1 * (1.0f + erff(t1 * 0.70710678118654752f));
                    __half h0 = __float2half_rn(t0);
                    __half h1 = __float2half_rn(t1);
                    uint32_t ph = ((uint32_t)__half_as_ushort(h1) << 16) | __half_as_ushort(h0);
                    *reinterpret_cast<uint32_t*>(OutT + (size_t)row * Ncols + col) = ph;
                } else {
                    float2 o; o.x = t0; o.y = t1;
                    *reinterpret_cast<float2*>(OutF + (size_t)row * Ncols + col) = o;
                }
            }
        }
    }
}

// ---------------- launcher ----------------------------------------------------
extern "C" void kernel_launch(void* const* d_in, const int* in_sizes, int n_in,
                              void* d_out, int out_size) {
    (void)in_sizes; (void)n_in; (void)out_size;
    const float* X  = (const float*)d_in[0];
    const float* W1 = (const float*)d_in[1];
    const float* b1 = (const float*)d_in[2];
    const float* W2 = (const float*)d_in[3];
    const float* b2 = (const float*)d_in[4];
    float* out = (float*)d_out;

    __half *Xh, *W1T, *W2T, *T;
    cudaGetSymbolAddress((void**)&Xh,  g_Xh);
    cudaGetSymbolAddress((void**)&W1T, g_W1T);
    cudaGetSymbolAddress((void**)&W2T, g_W2T);
    cudaGetSymbolAddress((void**)&T,   g_T);

    cudaFuncSetAttribute(hmma_gemm<D_SZ, true>,
                         cudaFuncAttributeMaxDynamicSharedMemorySize, SMEM_REQ);
    cudaFuncSetAttribute(hmma_gemm<H_SZ, false>,
                         cudaFuncAttributeMaxDynamicSharedMemorySize, SMEM_REQ);

    // 1) convert X to fp16
    convert_half_kernel<<<4096, 256>>>(X, Xh, M_TOT * D_SZ / 4);
    // 2) transpose weights into K-major fp16
    transpose_half_kernel<<<dim3(H_SZ / 32, D_SZ / 32), dim3(32, 8)>>>(W1, W1T, D_SZ, H_SZ);
    transpose_half_kernel<<<dim3(D_SZ / 32, H_SZ / 32), dim3(32, 8)>>>(W2, W2T, H_SZ, D_SZ);
    // 3) GEMM1: T = GELU(X @ W1 + b1), fp16 output
    hmma_gemm<D_SZ, true><<<dim3(H_SZ / GBN, M_TOT / GBM), NTHR, SMEM_REQ>>>(
        Xh, W1T, b1, T, nullptr, H_SZ);
    // 4) GEMM2: out = T @ W2 + b2, fp32 output
    hmma_gemm<H_SZ, false><<<dim3(D_SZ / GBN, M_TOT / GBM), NTHR, SMEM_REQ>>>(
        T, W2T, b2, nullptr, out, D_SZ);
    // 5) out[:,0,:] = X[:,0,:]
    copy_first_token_kernel<<<(B_SZ * D_SZ + 255) / 256, 256>>>(X, out);
}

// round 15
// speedup vs baseline: 1.0252x; 1.0252x over previous
#include <cuda_runtime.h>
#include <cuda_fp16.h>
#include <cstdint>
#include <math.h>

#define B_SZ 8
#define S_SZ 2048
#define D_SZ 1024
#define H_SZ 2048
#define M_TOT 16384

// ---------------- scratch (device globals) ------------------------------------
__device__ __half g_Xh[(size_t)M_TOT * D_SZ];    // X as fp16
__device__ __half g_W1T[(size_t)H_SZ * D_SZ];    // [N=2048][K=1024] fp16
__device__ __half g_W2T[(size_t)D_SZ * H_SZ];    // [N=1024][K=2048] fp16
__device__ __half g_T[(size_t)M_TOT * H_SZ];     // GEMM1 out, fp16

// ---------------- small PTX helpers (sm_80-level, compute_103-safe) ------------
static __device__ __forceinline__ uint32_t smem_u32(const void* p) {
    uint32_t a;
    asm("{ .reg .u64 t; cvta.to.shared.u64 t, %1; cvt.u32.u64 %0, t; }"
        : "=r"(a) : "l"(p));
    return a;
}
static __device__ __forceinline__ void cpasync16(uint32_t dst, const void* src) {
    asm volatile("cp.async.cg.shared.global [%0], [%1], 16;"
                 :: "r"(dst), "l"(src) : "memory");
}
static __device__ __forceinline__ void cp_commit() {
    asm volatile("cp.async.commit_group;" ::: "memory");
}
template<int N>
static __device__ __forceinline__ void cp_wait() {
    asm volatile("cp.async.wait_group %0;" :: "n"(N) : "memory");
}
static __device__ __forceinline__ void ldsm4(uint32_t* r, uint32_t addr) {
    asm volatile("ldmatrix.sync.aligned.m8n8.x4.shared.b16 {%0,%1,%2,%3}, [%4];"
                 : "=r"(r[0]), "=r"(r[1]), "=r"(r[2]), "=r"(r[3]) : "r"(addr));
}
static __device__ __forceinline__ void mma16816(float* d, const uint32_t* a,
                                                uint32_t b0, uint32_t b1) {
    asm volatile(
        "mma.sync.aligned.m16n8k16.row.col.f32.f16.f16.f32 "
        "{%0,%1,%2,%3}, {%4,%5,%6,%7}, {%8,%9}, {%0,%1,%2,%3};"
        : "+f"(d[0]), "+f"(d[1]), "+f"(d[2]), "+f"(d[3])
        : "r"(a[0]), "r"(a[1]), "r"(a[2]), "r"(a[3]), "r"(b0), "r"(b1));
}

// ---------------- prep kernels ------------------------------------------------
__global__ void convert_half_kernel(const float* __restrict__ X,
                                    __half* __restrict__ H, int n4) {
    int stride = gridDim.x * blockDim.x;
    for (int i = blockIdx.x * blockDim.x + threadIdx.x; i < n4; i += stride) {
        float4 v = reinterpret_cast<const float4*>(X)[i];
        uint2 p;
        p.x = ((uint32_t)__half_as_ushort(__float2half_rn(v.y)) << 16)
            | __half_as_ushort(__float2half_rn(v.x));
        p.y = ((uint32_t)__half_as_ushort(__float2half_rn(v.w)) << 16)
            | __half_as_ushort(__float2half_rn(v.z));
        reinterpret_cast<uint2*>(H)[i] = p;
    }
}

// W [R][C] fp32 -> WT [C][R] fp16
__global__ void transpose_half_kernel(const float* __restrict__ W,
                                      __half* __restrict__ T,
                                      int R, int C) {
    __shared__ float t[32][33];
    int c0 = blockIdx.x * 32, r0 = blockIdx.y * 32;
    int tx = threadIdx.x, ty = threadIdx.y;
    #pragma unroll
    for (int i = ty; i < 32; i += 8)
        t[i][tx] = W[(size_t)(r0 + i) * C + c0 + tx];
    __syncthreads();
    #pragma unroll
    for (int i = ty; i < 32; i += 8) {
        float x = t[tx][i];                 // = W[r0+tx][c0+i]
        T[(size_t)(c0 + i) * R + r0 + tx] = __float2half_rn(x);
    }
}

__global__ void copy_first_token_kernel(const float* __restrict__ X,
                                        float* __restrict__ out) {
    int i = blockIdx.x * blockDim.x + threadIdx.x;
    if (i >= B_SZ * D_SZ) return;
    int b = i >> 10, d = i & 1023;
    size_t off = ((size_t)b * S_SZ) * D_SZ + d;
    out[off] = X[off];
}

// ---------------- HMMA (mma.sync) fp16 GEMM ------------------------------------
// C[M,N] = act(A·B^T + bias); A, B fp16 K-major; fp32 accum.
// CTA tile 64x128x64, 3-stage cp.async (72KB), 4 warps of 32x64, 3 CTAs/SM.
// Fragment double-buffering hides LDSM latency inside the 4 k16-steps/chunk.
#define GBM 64
#define GBN 128
#define GBK 64
#define NTHR 128
#define STAGES 3
#define STG_B 24576                 // A 8K | B 16K
#define B_O   8192
#define SMEM_REQ (STAGES * STG_B)   // 72KB

#define LOAD_FRAGS(BUF, SB, STEP) do {                                         \
    const uint32_t acx_ = (uint32_t)((STEP) * 2) + a_c;                        \
    const uint32_t bcx_ = (uint32_t)((STEP) * 2) + b_c;                        \
    _Pragma("unroll")                                                          \
    for (int mi_ = 0; mi_ < 2; ++mi_)                                          \
        ldsm4(Ah[BUF][mi_], (SB) + aAddr[mi_] + ((acx_ ^ aSw[mi_]) << 4));     \
    _Pragma("unroll")                                                          \
    for (int ni_ = 0; ni_ < 4; ++ni_)                                          \
        ldsm4(Bh[BUF][ni_], (SB) + bAddr[ni_] + ((bcx_ ^ bSw[ni_]) << 4));     \
} while (0)

#define MMA_STEP(BUF) do {                                                     \
    _Pragma("unroll")                                                          \
    for (int mi_ = 0; mi_ < 2; ++mi_) {                                        \
        _Pragma("unroll")                                                      \
        for (int nj_ = 0; nj_ < 8; ++nj_) {                                    \
            const int ni_ = nj_ >> 1, h_ = (nj_ & 1) * 2;                      \
            mma16816(acc[mi_][nj_], Ah[BUF][mi_], Bh[BUF][ni_][h_],            \
                     Bh[BUF][ni_][h_ + 1]);                                    \
        }                                                                      \
    }                                                                          \
} while (0)

template<int K_TOT, bool FUSE1>
__global__ __launch_bounds__(NTHR, 3)
void hmma_gemm(const __half* __restrict__ Amat,
               const __half* __restrict__ Bmat,
               const float* __restrict__ bias,
               __half* __restrict__ OutT,
               float* __restrict__ OutF,
               int Ncols)
{
    extern __shared__ char smem_raw[];
    const uint32_t sbase = smem_u32(smem_raw);

    const int tid = threadIdx.x;
    const int wid = tid >> 5;
    const int l   = tid & 31;
    const int m0  = blockIdx.y * GBM;
    const int n0  = blockIdx.x * GBN;
    const int wm  = wid & 1;        // 2 warp-rows of 32
    const int wn  = wid >> 1;       // 2 warp-cols of 64

    // ---- global->smem load plan: 12 x 16B units per thread ------------------
    // rows are 128B (64 fp16). thread: r0 = tid>>3 (0..15), cc = tid&7.
    const char* pmA;
    const char* pmB;
    {
        const int r0 = tid >> 3, cc = tid & 7;
        pmA = (const char*)(Amat + (size_t)(m0 + r0) * K_TOT) + cc * 16;
        pmB = (const char*)(Bmat + (size_t)(n0 + r0) * K_TOT) + cc * 16;
    }
    // swizzle: chunk' = cc ^ (row & 7); (row+16j)&7 == r0&7, so s0 is constant
    const uint32_t s0 = (uint32_t)((tid >> 3) * 128)
                      + ((uint32_t)((tid & 7) ^ ((tid >> 3) & 7)) << 4);

    // ---- ldmatrix address pieces -------------------------------------------
    uint32_t aAddr[2], aSw[2], bAddr[4], bSw[4];
    #pragma unroll
    for (int mi = 0; mi < 2; ++mi) {
        int row = wm * 32 + mi * 16 + ((l >> 3) & 1) * 8 + (l & 7);
        aAddr[mi] = (uint32_t)row * 128;
        aSw[mi]   = (uint32_t)(row & 7);
    }
    #pragma unroll
    for (int ni = 0; ni < 4; ++ni) {
        int row = wn * 64 + ni * 16 + ((l >> 4) & 1) * 8 + (l & 7);
        bAddr[ni] = B_O + (uint32_t)row * 128;
        bSw[ni]   = (uint32_t)(row & 7);
    }
    const uint32_t a_c = (uint32_t)(l >> 4);
    const uint32_t b_c = (uint32_t)((l >> 3) & 1);

    float acc[2][8][4];
    #pragma unroll
    for (int i = 0; i < 2; ++i)
        #pragma unroll
        for (int j = 0; j < 8; ++j)
            #pragma unroll
            for (int q = 0; q < 4; ++q) acc[i][j][q] = 0.f;

    uint32_t Ah[2][2][4], Bh[2][4][4];

    constexpr int NC = K_TOT / GBK;

    // unit i: 0..3 -> A row-block i; 4..11 -> B row-block i-4
    auto unit_src = [&](int i, int chunk) -> const char* {
        const char* base = (i < 4) ? pmA : pmB;
        const int kb = (i < 4) ? i : (i - 4);
        return base + (size_t)kb * 16 * K_TOT * 2 + (size_t)chunk * 128;
    };
    auto unit_dst = [&](int i, uint32_t sb) -> uint32_t {
        const int kb = (i < 4) ? i : (i - 4);
        const uint32_t mb = (i < 4) ? 0u : B_O;
        return sb + mb + (uint32_t)kb * 2048 + s0;
    };

    // prologue: fill stages 0 and 1 (chunks 0, 1)
    #pragma unroll
    for (int s = 0; s < 2; ++s) {
        const uint32_t sb = sbase + (uint32_t)s * STG_B;
        #pragma unroll
        for (int i = 0; i < 12; ++i)
            cpasync16(unit_dst(i, sb), unit_src(i, s));
        cp_commit();
    }

    #pragma unroll 1
    for (int c = 0; c < NC; ++c) {
        cp_wait<1>();                // chunk c complete (issued 2 chunks ago)
        __syncthreads();

        // prefetch chunk c+2 into the slot vacated by chunk c-1
        const int pf = c + 2;
        if (pf < NC) {
            const uint32_t sbpf = sbase + (uint32_t)(pf % STAGES) * STG_B;
            #pragma unroll
            for (int i = 0; i < 12; ++i)
                cpasync16(unit_dst(i, sbpf), unit_src(i, pf));
        }
        cp_commit();

        const uint32_t sb = sbase + (uint32_t)(c % STAGES) * STG_B;
        LOAD_FRAGS(0, sb, 0);
        #pragma unroll
        for (int step = 0; step < 4; ++step) {
            if (step < 3) LOAD_FRAGS((step + 1) & 1, sb, step + 1);
            MMA_STEP(step & 1);
        }
    }

    // ---- epilogue -----------------------------------------------------------
    const int r_base = m0 + wm * 32 + (l >> 2);
    const int c_base = n0 + wn * 64 + (l & 3) * 2;
    #pragma unroll
    for (int mi = 0; mi < 2; ++mi) {
        #pragma unroll
        for (int nj = 0; nj < 8; ++nj) {
            const int col = c_base + nj * 8;
            const float bb0 = __ldg(bias + col);
            const float bb1 = __ldg(bias + col + 1);
            #pragma unroll
            for (int hh = 0; hh < 2; ++hh) {
                const int row = r_base + mi * 16 + hh * 8;
                float t0 = acc[mi][nj][hh * 2 + 0] + bb0;
                float t1 = acc[mi][nj][hh * 2 + 1] + bb1;
                if (FUSE1) {
                    t0 = 0.5f * t0 * (1.0f + erff(t0 * 0.70710678118654752f));
                    t1 = 0.5f * t1 * (1.0f + erff(t1 * 0.70710678118654752f));
                    __half h0 = __float2half_rn(t0);
                    __half h1 = __float2half_rn(t1);
                    uint32_t ph = ((uint32_t)__half_as_ushort(h1) << 16) | __half_as_ushort(h0);
                    *reinterpret_cast<uint32_t*>(OutT + (size_t)row * Ncols + col) = ph;
                } else {
                    float2 o; o.x = t0; o.y = t1;
                    *reinterpret_cast<float2*>(OutF + (size_t)row * Ncols + col) = o;
                }
            }
        }
    }
}

// ---------------- launcher ----------------------------------------------------
extern "C" void kernel_launch(void* const* d_in, const int* in_sizes, int n_in,
                              void* d_out, int out_size) {
    (void)in_sizes; (void)n_in; (void)out_size;
    const float* X  = (const float*)d_in[0];
    const float* W1 = (const float*)d_in[1];
    const float* b1 = (const float*)d_in[2];
    const float* W2 = (const float*)d_in[3];
    const float* b2 = (const float*)d_in[4];
    float* out = (float*)d_out;

    __half *Xh, *W1T, *W2T, *T;
    cudaGetSymbolAddress((void**)&Xh,  g_Xh);
    cudaGetSymbolAddress((void**)&W1T, g_W1T);
    cudaGetSymbolAddress((void**)&W2T, g_W2T);
    cudaGetSymbolAddress((void**)&T,   g_T);

    cudaFuncSetAttribute(hmma_gemm<D_SZ, true>,
                         cudaFuncAttributeMaxDynamicSharedMemorySize, SMEM_REQ);
    cudaFuncSetAttribute(hmma_gemm<H_SZ, false>,
                         cudaFuncAttributeMaxDynamicSharedMemorySize, SMEM_REQ);

    // 1) convert X to fp16
    convert_half_kernel<<<4096, 256>>>(X, Xh, M_TOT * D_SZ / 4);
    // 2) transpose weights into K-major fp16
    transpose_half_kernel<<<dim3(H_SZ / 32, D_SZ / 32), dim3(32, 8)>>>(W1, W1T, D_SZ, H_SZ);
    transpose_half_kernel<<<dim3(D_SZ / 32, H_SZ / 32), dim3(32, 8)>>>(W2, W2T, H_SZ, D_SZ);
    // 3) GEMM1: T = GELU(X @ W1 + b1), fp16 output
    hmma_gemm<D_SZ, true><<<dim3(H_SZ / GBN, M_TOT / GBM), NTHR, SMEM_REQ>>>(
        Xh, W1T, b1, T, nullptr, H_SZ);
    // 4) GEMM2: out = T @ W2 + b2, fp32 output
    hmma_gemm<H_SZ, false><<<dim3(D_SZ / GBN, M_TOT / GBM), NTHR, SMEM_REQ>>>(
        T, W2T, b2, nullptr, out, D_SZ);
    // 5) out[:,0,:] = X[:,0,:]
    copy_first_token_kernel<<<(B_SZ * D_SZ + 255) / 256, 256>>>(X, out);
}